// round 5
// baseline (speedup 1.0000x reference)
#include <cuda_runtime.h>

#define NN 50000
#define EE 800000
#define FIN 128
#define HH 100
#define CC 16
#define SCAN_B 512
#define NCHUNK ((NN + SCAN_B - 1) / SCAN_B)   // 98

// ---- scratch (device globals; no allocations) ----
__device__ float g_dinv[NN];
__device__ int   g_cnt[NN];
__device__ int   g_incl[NN];
__device__ int   g_bsum[NCHUNK];
__device__ int   g_boff[NCHUNK];
__device__ int   g_rowptr[NN + 1];
__device__ int   g_cur[NN];
__device__ int   g_csr_src[EE];
__device__ float g_csr_w[EE];
__device__ float g_h1[NN * HH];       // x @ W1
__device__ float g_h1p[NN * HH];      // propagated layer-1
__device__ float g_h2[NN * CC];       // a1 @ W2

// ================= CSR build =================

__global__ void k_zero() {
    int i = blockIdx.x * blockDim.x + threadIdx.x;
    if (i < NN) g_cnt[i] = 0;
}

__global__ void k_count(const int* __restrict__ dst) {
    int e = blockIdx.x * blockDim.x + threadIdx.x;
    if (e < EE) atomicAdd(&g_cnt[dst[e]], 1);
}

__global__ __launch_bounds__(SCAN_B) void k_scan1() {
    __shared__ int sh[SCAN_B];
    int t = threadIdx.x;
    int i = blockIdx.x * SCAN_B + t;
    int v = (i < NN) ? g_cnt[i] : 0;
    sh[t] = v;
    __syncthreads();
#pragma unroll
    for (int off = 1; off < SCAN_B; off <<= 1) {
        int a = (t >= off) ? sh[t - off] : 0;
        __syncthreads();
        sh[t] += a;
        __syncthreads();
    }
    if (i < NN) g_incl[i] = sh[t];
    if (t == SCAN_B - 1) g_bsum[blockIdx.x] = sh[t];
}

// parallel scan of the NCHUNK block sums (one block, 128 threads)
__global__ __launch_bounds__(128) void k_scan2() {
    __shared__ int sh[128];
    int t = threadIdx.x;
    int v = (t < NCHUNK) ? g_bsum[t] : 0;
    sh[t] = v;
    __syncthreads();
#pragma unroll
    for (int off = 1; off < 128; off <<= 1) {
        int a = (t >= off) ? sh[t - off] : 0;
        __syncthreads();
        sh[t] += a;
        __syncthreads();
    }
    if (t < NCHUNK) g_boff[t] = sh[t] - v;   // exclusive
}

__global__ __launch_bounds__(SCAN_B) void k_scan3() {
    int i = blockIdx.x * SCAN_B + threadIdx.x;
    if (i < NN) {
        int cnt = g_cnt[i];
        int excl = g_incl[i] - cnt + g_boff[blockIdx.x];
        g_rowptr[i] = excl;
        g_cur[i] = excl;
        g_dinv[i] = rsqrtf((float)(cnt + 1));  // +1 self loop
    }
    if (i == 0) g_rowptr[NN] = EE;
}

__global__ void k_scatter(const int* __restrict__ src, const int* __restrict__ dst) {
    int e = blockIdx.x * blockDim.x + threadIdx.x;
    if (e >= EE) return;
    int s = src[e], d = dst[e];
    int pos = atomicAdd(&g_cur[d], 1);
    g_csr_src[pos] = s;
    g_csr_w[pos] = g_dinv[s] * g_dinv[d];
}

// ================ GEMM1: h1 = x @ W1 (50000x128 @ 128x100) ================
// 128x128 tile (N padded to 128), 256 threads, 8x8 register tile, K-step 32.
// A tile row-major (clean float4 STS, scalar broadcast LDS reads);
// B tile read as 2x LDS.128 per k. 10 LDS-issues per 64 FFMA per k.

__global__ __launch_bounds__(256) void k_gemm1(const float* __restrict__ x,
                                               const float* __restrict__ W1) {
    __shared__ float As[128][36];   // pad 36 -> +4 bank shift per row
    __shared__ float Bs[32][128];

    const int m0  = blockIdx.x * 128;
    const int tid = threadIdx.x;
    const int tr  = tid >> 4;       // 0..15 (row group)
    const int tc  = tid & 15;       // 0..15 (col group)

    float acc[8][8];
#pragma unroll
    for (int i = 0; i < 8; i++)
#pragma unroll
        for (int j = 0; j < 8; j++) acc[i][j] = 0.0f;

#pragma unroll
    for (int k0 = 0; k0 < FIN; k0 += 32) {
        // A tile: 128 rows x 32 k = 1024 float4, 4 per thread (row-major)
#pragma unroll
        for (int u = 0; u < 4; u++) {
            int chunk = tid + u * 256;          // 0..1023
            int row = chunk >> 3;               // 0..127
            int kk  = (chunk & 7) << 2;         // 0,4,...,28
            int gr = m0 + row;
            float4 v = make_float4(0.f, 0.f, 0.f, 0.f);
            if (gr < NN) v = *(const float4*)&x[gr * FIN + k0 + kk];
            *(float4*)&As[row][kk] = v;
        }
        // B tile: 32 k x 128 cols (cols >= 100 zero), scalar guarded loads
#pragma unroll
        for (int u = 0; u < 4; u++) {
            int chunk = tid + u * 256;          // 0..1023
            int k = chunk >> 5;                 // 0..31
            int c = (chunk & 31) << 2;          // 0,4,...,124
            const float* wrow = W1 + (k0 + k) * HH;
            float4 v;
            v.x = (c + 0 < HH) ? wrow[c + 0] : 0.0f;
            v.y = (c + 1 < HH) ? wrow[c + 1] : 0.0f;
            v.z = (c + 2 < HH) ? wrow[c + 2] : 0.0f;
            v.w = (c + 3 < HH) ? wrow[c + 3] : 0.0f;
            *(float4*)&Bs[k][c] = v;
        }
        __syncthreads();

#pragma unroll
        for (int k = 0; k < 32; k++) {
            float a[8];
#pragma unroll
            for (int i = 0; i < 4; i++) a[i] = As[tr * 4 + i][k];
#pragma unroll
            for (int i = 0; i < 4; i++) a[4 + i] = As[64 + tr * 4 + i][k];
            float4 b0 = *(const float4*)&Bs[k][tc * 4];
            float4 b1 = *(const float4*)&Bs[k][64 + tc * 4];
            float bv[8] = {b0.x, b0.y, b0.z, b0.w, b1.x, b1.y, b1.z, b1.w};
#pragma unroll
            for (int i = 0; i < 8; i++)
#pragma unroll
                for (int j = 0; j < 8; j++) acc[i][j] += a[i] * bv[j];
        }
        __syncthreads();
    }

    // store: rows {tr*4+i, 64+tr*4+i}, col groups {tc*4, 64+tc*4}
#pragma unroll
    for (int i = 0; i < 8; i++) {
        int r = m0 + ((i < 4) ? (tr * 4 + i) : (64 + tr * 4 + (i - 4)));
        if (r >= NN) continue;
        float* orow = g_h1 + r * HH;
        // first col group: cols tc*4..tc*4+3 (< 64 < HH always), 16B aligned
        float4 o0 = make_float4(acc[i][0], acc[i][1], acc[i][2], acc[i][3]);
        *(float4*)&orow[tc * 4] = o0;
        // second col group: cols 64+tc*4.. ; full float4 iff 64+tc*4+3 < HH
        int c1 = 64 + tc * 4;
        if (c1 + 3 < HH) {
            float4 o1 = make_float4(acc[i][4], acc[i][5], acc[i][6], acc[i][7]);
            *(float4*)&orow[c1] = o1;
        } else {
#pragma unroll
            for (int j = 0; j < 4; j++)
                if (c1 + j < HH) orow[c1 + j] = acc[i][4 + j];
        }
    }
}

// ============ prop1: gather per destination node (warp/node) ============

__global__ __launch_bounds__(256) void k_prop1() {
    int w = (blockIdx.x * blockDim.x + threadIdx.x) >> 5;
    int lane = threadIdx.x & 31;
    if (w >= NN) return;
    int beg = g_rowptr[w];
    int end = g_rowptr[w + 1];
    float dv = g_dinv[w];
    float sc = dv * dv;                       // self-loop coefficient
    const float* sr = g_h1 + w * HH;
    bool tail = (lane < HH - 96);

    float a0 = sr[lane] * sc;
    float a1 = sr[32 + lane] * sc;
    float a2 = sr[64 + lane] * sc;
    float a3 = tail ? sr[96 + lane] * sc : 0.f;

    int e = beg;
    for (; e + 4 <= end; e += 4) {
        int s0 = g_csr_src[e],     s1 = g_csr_src[e + 1];
        int s2 = g_csr_src[e + 2], s3 = g_csr_src[e + 3];
        float c0 = g_csr_w[e],     c1 = g_csr_w[e + 1];
        float c2 = g_csr_w[e + 2], c3 = g_csr_w[e + 3];
        const float* r0 = g_h1 + s0 * HH;
        const float* r1 = g_h1 + s1 * HH;
        const float* r2 = g_h1 + s2 * HH;
        const float* r3 = g_h1 + s3 * HH;
        float x00 = r0[lane], x01 = r0[32 + lane], x02 = r0[64 + lane];
        float x10 = r1[lane], x11 = r1[32 + lane], x12 = r1[64 + lane];
        float x20 = r2[lane], x21 = r2[32 + lane], x22 = r2[64 + lane];
        float x30 = r3[lane], x31 = r3[32 + lane], x32 = r3[64 + lane];
        float x03 = tail ? r0[96 + lane] : 0.f;
        float x13 = tail ? r1[96 + lane] : 0.f;
        float x23 = tail ? r2[96 + lane] : 0.f;
        float x33 = tail ? r3[96 + lane] : 0.f;
        a0 += c0 * x00 + c1 * x10 + c2 * x20 + c3 * x30;
        a1 += c0 * x01 + c1 * x11 + c2 * x21 + c3 * x31;
        a2 += c0 * x02 + c1 * x12 + c2 * x22 + c3 * x32;
        a3 += c0 * x03 + c1 * x13 + c2 * x23 + c3 * x33;
    }
    for (; e < end; e++) {
        int s = g_csr_src[e];
        float c = g_csr_w[e];
        const float* r = g_h1 + s * HH;
        a0 += c * r[lane];
        a1 += c * r[32 + lane];
        a2 += c * r[64 + lane];
        if (tail) a3 += c * r[96 + lane];
    }

    float* o = g_h1p + w * HH;
    o[lane] = a0;
    o[32 + lane] = a1;
    o[64 + lane] = a2;
    if (tail) o[96 + lane] = a3;
}

// ===== GEMM2: h2 = leaky(h1p + b1) @ W2  (50000x100 @ 100x16) =====

__global__ __launch_bounds__(256) void k_gemm2(const float* __restrict__ b1,
                                               const float* __restrict__ W2) {
    __shared__ float w2s[HH * CC];
    __shared__ float a1s[16][HH];
    int tid = threadIdx.x;
    int r0  = blockIdx.x * 16;

    for (int i = tid; i < HH * CC; i += 256) w2s[i] = W2[i];
    for (int i = tid; i < 16 * HH; i += 256) {
        int r = i / HH, c = i % HH;
        int gr = r0 + r;
        float v = 0.0f;
        if (gr < NN) {
            v = g_h1p[gr * HH + c] + b1[c];
            v = (v > 0.0f) ? v : 0.01f * v;
        }
        a1s[r][c] = v;
    }
    __syncthreads();

    int r = tid >> 4;
    int c = tid & 15;
    float acc = 0.0f;
#pragma unroll
    for (int k = 0; k < HH; k++) acc += a1s[r][k] * w2s[k * CC + c];
    int gr = r0 + r;
    if (gr < NN) g_h2[gr * CC + c] = acc;
}

// ===== prop2 + bias + log_softmax fused (4 threads per node) =====

__global__ __launch_bounds__(256) void k_prop2_final(const float* __restrict__ b2,
                                                     float* __restrict__ out) {
    int t = blockIdx.x * blockDim.x + threadIdx.x;
    int node = t >> 2;
    int q = t & 3;
    if (node >= NN) return;

    int beg = g_rowptr[node];
    int end = g_rowptr[node + 1];
    float dv = g_dinv[node];
    float sc = dv * dv;

    float4 v = *(const float4*)&g_h2[node * CC + 4 * q];
    float4 acc = make_float4(v.x * sc, v.y * sc, v.z * sc, v.w * sc);

    int e = beg;
    for (; e + 2 <= end; e += 2) {
        int s0 = g_csr_src[e], s1 = g_csr_src[e + 1];
        float c0 = g_csr_w[e], c1 = g_csr_w[e + 1];
        float4 v0 = *(const float4*)&g_h2[s0 * CC + 4 * q];
        float4 v1 = *(const float4*)&g_h2[s1 * CC + 4 * q];
        acc.x += c0 * v0.x + c1 * v1.x;
        acc.y += c0 * v0.y + c1 * v1.y;
        acc.z += c0 * v0.z + c1 * v1.z;
        acc.w += c0 * v0.w + c1 * v1.w;
    }
    for (; e < end; e++) {
        int s = g_csr_src[e];
        float c = g_csr_w[e];
        float4 v0 = *(const float4*)&g_h2[s * CC + 4 * q];
        acc.x += c * v0.x; acc.y += c * v0.y;
        acc.z += c * v0.z; acc.w += c * v0.w;
    }

    float4 bv = ((const float4*)b2)[q];
    acc.x += bv.x; acc.y += bv.y; acc.z += bv.z; acc.w += bv.w;

    float m = fmaxf(fmaxf(acc.x, acc.y), fmaxf(acc.z, acc.w));
    m = fmaxf(m, __shfl_xor_sync(0xffffffffu, m, 1, 4));
    m = fmaxf(m, __shfl_xor_sync(0xffffffffu, m, 2, 4));
    float s = expf(acc.x - m) + expf(acc.y - m) + expf(acc.z - m) + expf(acc.w - m);
    s += __shfl_xor_sync(0xffffffffu, s, 1, 4);
    s += __shfl_xor_sync(0xffffffffu, s, 2, 4);
    float ls = m + logf(s);

    float4 o = make_float4(acc.x - ls, acc.y - ls, acc.z - ls, acc.w - ls);
    *(float4*)&out[node * CC + 4 * q] = o;
}

// ================= launcher =================

extern "C" void kernel_launch(void* const* d_in, const int* in_sizes, int n_in,
                              void* d_out, int out_size) {
    const float* x  = (const float*)d_in[0];
    const float* W1 = (const float*)d_in[1];
    const float* b1 = (const float*)d_in[2];
    const float* W2 = (const float*)d_in[3];
    const float* b2 = (const float*)d_in[4];
    const int*   ei = (const int*)d_in[5];
    const int* src = ei;
    const int* dst = ei + EE;
    float* out = (float*)d_out;

    // CSR build
    k_zero<<<(NN + 255) / 256, 256>>>();
    k_count<<<(EE + 255) / 256, 256>>>(dst);
    k_scan1<<<NCHUNK, SCAN_B>>>();
    k_scan2<<<1, 128>>>();
    k_scan3<<<NCHUNK, SCAN_B>>>();
    k_scatter<<<(EE + 255) / 256, 256>>>(src, dst);

    // layer 1
    k_gemm1<<<(NN + 127) / 128, 256>>>(x, W1);
    k_prop1<<<(NN * 32 + 255) / 256, 256>>>();

    // layer 2 + output
    k_gemm2<<<(NN + 15) / 16, 256>>>(b1, W2);
    k_prop2_final<<<(NN * 4 + 255) / 256, 256>>>(b2, out);
}

// round 8
// speedup vs baseline: 1.4472x; 1.4472x over previous
#include <cuda_runtime.h>

#define NN 50000
#define EE 800000
#define FIN 128
#define HH 100
#define CC 16
#define SCAN_B 512
#define NCHUNK ((NN + SCAN_B - 1) / SCAN_B)   // 98

// ---- scratch (device globals; no allocations) ----
__device__ float g_dinv[NN];
__device__ int   g_cnt[NN];
__device__ int   g_incl[NN];
__device__ int   g_bsum[NCHUNK];
__device__ int   g_boff[NCHUNK];
__device__ int   g_rowptr[NN + 1];
__device__ int   g_cur[NN];
__device__ int   g_csr_src[EE];
__device__ float g_csr_w[EE];
__device__ float g_h1[NN * HH];       // x @ W1
__device__ float g_h1p[NN * HH];      // propagated layer-1
__device__ float g_h2[NN * CC];       // a1 @ W2

// ================= CSR build =================

__global__ void k_zero() {
    int i = blockIdx.x * blockDim.x + threadIdx.x;
    if (i < NN) g_cnt[i] = 0;
}

__global__ void k_count(const int* __restrict__ dst) {
    int e = blockIdx.x * blockDim.x + threadIdx.x;
    if (e < EE) atomicAdd(&g_cnt[dst[e]], 1);
}

__global__ __launch_bounds__(SCAN_B) void k_scan1() {
    __shared__ int sh[SCAN_B];
    int t = threadIdx.x;
    int i = blockIdx.x * SCAN_B + t;
    int v = (i < NN) ? g_cnt[i] : 0;
    sh[t] = v;
    __syncthreads();
#pragma unroll
    for (int off = 1; off < SCAN_B; off <<= 1) {
        int a = (t >= off) ? sh[t - off] : 0;
        __syncthreads();
        sh[t] += a;
        __syncthreads();
    }
    if (i < NN) g_incl[i] = sh[t];
    if (t == SCAN_B - 1) g_bsum[blockIdx.x] = sh[t];
}

// parallel scan of the NCHUNK block sums (one block, 128 threads)
__global__ __launch_bounds__(128) void k_scan2() {
    __shared__ int sh[128];
    int t = threadIdx.x;
    int v = (t < NCHUNK) ? g_bsum[t] : 0;
    sh[t] = v;
    __syncthreads();
#pragma unroll
    for (int off = 1; off < 128; off <<= 1) {
        int a = (t >= off) ? sh[t - off] : 0;
        __syncthreads();
        sh[t] += a;
        __syncthreads();
    }
    if (t < NCHUNK) g_boff[t] = sh[t] - v;   // exclusive
}

__global__ __launch_bounds__(SCAN_B) void k_scan3() {
    int i = blockIdx.x * SCAN_B + threadIdx.x;
    if (i < NN) {
        int cnt = g_cnt[i];
        int excl = g_incl[i] - cnt + g_boff[blockIdx.x];
        g_rowptr[i] = excl;
        g_cur[i] = excl;
        g_dinv[i] = rsqrtf((float)(cnt + 1));  // +1 self loop
    }
    if (i == 0) g_rowptr[NN] = EE;
}

__global__ void k_scatter(const int* __restrict__ src, const int* __restrict__ dst) {
    int e = blockIdx.x * blockDim.x + threadIdx.x;
    if (e >= EE) return;
    int s = src[e], d = dst[e];
    int pos = atomicAdd(&g_cur[d], 1);
    g_csr_src[pos] = s;
    g_csr_w[pos] = g_dinv[s] * g_dinv[d];
}

// ================ GEMM1: h1 = x @ W1 (50000x128 @ 128x100) ================
// Proven v1: 64-row tile, N padded to 128, 256 threads, 4x8 register tile.

__global__ __launch_bounds__(256) void k_gemm1(const float* __restrict__ x,
                                               const float* __restrict__ W1) {
    __shared__ float As[64][36];
    __shared__ float Bs[32][128];

    const int m0  = blockIdx.x * 64;
    const int tid = threadIdx.x;
    const int tx  = tid & 15;
    const int ty  = tid >> 4;

    float acc[4][8];
#pragma unroll
    for (int i = 0; i < 4; i++)
#pragma unroll
        for (int j = 0; j < 8; j++) acc[i][j] = 0.0f;

#pragma unroll
    for (int k0 = 0; k0 < FIN; k0 += 32) {
        {
            int row = tid >> 3;
            int kk  = (tid & 7) << 2;
#pragma unroll
            for (int rr = 0; rr < 64; rr += 32) {
                int gr = m0 + row + rr;
                float4 v = make_float4(0.f, 0.f, 0.f, 0.f);
                if (gr < NN) v = *(const float4*)&x[gr * FIN + k0 + kk];
                *(float4*)&As[row + rr][kk] = v;
            }
        }
#pragma unroll
        for (int i = 0; i < 16; i++) {
            int idx = tid + i * 256;
            int k = idx >> 7, c = idx & 127;
            Bs[k][c] = (c < HH) ? W1[(k0 + k) * HH + c] : 0.0f;
        }
        __syncthreads();

#pragma unroll
        for (int k = 0; k < 32; k++) {
            float a[4], b[8];
#pragma unroll
            for (int i = 0; i < 4; i++) a[i] = As[ty + 16 * i][k];
#pragma unroll
            for (int j = 0; j < 8; j++) b[j] = Bs[k][tx + 16 * j];
#pragma unroll
            for (int i = 0; i < 4; i++)
#pragma unroll
                for (int j = 0; j < 8; j++) acc[i][j] += a[i] * b[j];
        }
        __syncthreads();
    }

#pragma unroll
    for (int i = 0; i < 4; i++) {
        int r = m0 + ty + 16 * i;
        if (r < NN) {
#pragma unroll
            for (int j = 0; j < 8; j++) {
                int c = tx + 16 * j;
                if (c < HH) g_h1[r * HH + c] = acc[i][j];
            }
        }
    }
}

// ============ prop1: gather per destination node (warp/node) ============

__global__ __launch_bounds__(256) void k_prop1() {
    int w = (blockIdx.x * blockDim.x + threadIdx.x) >> 5;
    int lane = threadIdx.x & 31;
    if (w >= NN) return;
    int beg = g_rowptr[w];
    int end = g_rowptr[w + 1];
    float dv = g_dinv[w];
    float sc = dv * dv;                       // self-loop coefficient
    const float* sr = g_h1 + w * HH;
    bool tail = (lane < HH - 96);

    float a0 = sr[lane] * sc;
    float a1 = sr[32 + lane] * sc;
    float a2 = sr[64 + lane] * sc;
    float a3 = tail ? sr[96 + lane] * sc : 0.f;

    int e = beg;
    for (; e + 4 <= end; e += 4) {
        int s0 = g_csr_src[e],     s1 = g_csr_src[e + 1];
        int s2 = g_csr_src[e + 2], s3 = g_csr_src[e + 3];
        float c0 = g_csr_w[e],     c1 = g_csr_w[e + 1];
        float c2 = g_csr_w[e + 2], c3 = g_csr_w[e + 3];
        const float* r0 = g_h1 + s0 * HH;
        const float* r1 = g_h1 + s1 * HH;
        const float* r2 = g_h1 + s2 * HH;
        const float* r3 = g_h1 + s3 * HH;
        float x00 = r0[lane], x01 = r0[32 + lane], x02 = r0[64 + lane];
        float x10 = r1[lane], x11 = r1[32 + lane], x12 = r1[64 + lane];
        float x20 = r2[lane], x21 = r2[32 + lane], x22 = r2[64 + lane];
        float x30 = r3[lane], x31 = r3[32 + lane], x32 = r3[64 + lane];
        float x03 = tail ? r0[96 + lane] : 0.f;
        float x13 = tail ? r1[96 + lane] : 0.f;
        float x23 = tail ? r2[96 + lane] : 0.f;
        float x33 = tail ? r3[96 + lane] : 0.f;
        a0 += c0 * x00 + c1 * x10 + c2 * x20 + c3 * x30;
        a1 += c0 * x01 + c1 * x11 + c2 * x21 + c3 * x31;
        a2 += c0 * x02 + c1 * x12 + c2 * x22 + c3 * x32;
        a3 += c0 * x03 + c1 * x13 + c2 * x23 + c3 * x33;
    }
    for (; e < end; e++) {
        int s = g_csr_src[e];
        float c = g_csr_w[e];
        const float* r = g_h1 + s * HH;
        a0 += c * r[lane];
        a1 += c * r[32 + lane];
        a2 += c * r[64 + lane];
        if (tail) a3 += c * r[96 + lane];
    }

    float* o = g_h1p + w * HH;
    o[lane] = a0;
    o[32 + lane] = a1;
    o[64 + lane] = a2;
    if (tail) o[96 + lane] = a3;
}

// ===== GEMM2: h2 = leaky(h1p + b1) @ W2  (50000x100 @ 100x16) =====
// 64 rows/block, 256 threads; thread computes 4 outputs:
// per k: 1 scalar LDS (a, 4-thread broadcast) + 1 LDS.128 (w2) + 4 FFMA.

__global__ __launch_bounds__(256) void k_gemm2(const float* __restrict__ b1,
                                               const float* __restrict__ W2) {
    __shared__ float w2s[HH * CC];      // [k][c] row-major, 1600 floats
    __shared__ float a1s[64][HH];       // 6400 floats
    int tid = threadIdx.x;
    int r0  = blockIdx.x * 64;

    for (int i = tid; i < HH * CC; i += 256) w2s[i] = W2[i];
#pragma unroll
    for (int u = 0; u < 25; u++) {
        int i = tid + u * 256;          // 0..6399
        int r = i / HH, c = i % HH;
        int gr = r0 + r;
        float v = 0.0f;
        if (gr < NN) {
            v = g_h1p[gr * HH + c] + b1[c];
            v = (v > 0.0f) ? v : 0.01f * v;
        }
        a1s[r][c] = v;
    }
    __syncthreads();

    int r = tid >> 2;        // 0..63
    int q = tid & 3;         // 0..3 -> cols 4q..4q+3
    float4 acc = make_float4(0.f, 0.f, 0.f, 0.f);
#pragma unroll
    for (int k = 0; k < HH; k++) {
        float a = a1s[r][k];
        float4 w = *(const float4*)&w2s[k * CC + 4 * q];
        acc.x += a * w.x;
        acc.y += a * w.y;
        acc.z += a * w.z;
        acc.w += a * w.w;
    }
    int gr = r0 + r;
    if (gr < NN) *(float4*)&g_h2[gr * CC + 4 * q] = acc;
}

// ===== prop2 + bias + log_softmax fused (4 threads per node) =====

__global__ __launch_bounds__(256) void k_prop2_final(const float* __restrict__ b2,
                                                     float* __restrict__ out) {
    int t = blockIdx.x * blockDim.x + threadIdx.x;
    int node = t >> 2;
    int q = t & 3;
    if (node >= NN) return;

    int beg = g_rowptr[node];
    int end = g_rowptr[node + 1];
    float dv = g_dinv[node];
    float sc = dv * dv;

    float4 v = *(const float4*)&g_h2[node * CC + 4 * q];
    float4 acc = make_float4(v.x * sc, v.y * sc, v.z * sc, v.w * sc);

    int e = beg;
    for (; e + 4 <= end; e += 4) {
        int s0 = g_csr_src[e],     s1 = g_csr_src[e + 1];
        int s2 = g_csr_src[e + 2], s3 = g_csr_src[e + 3];
        float c0 = g_csr_w[e],     c1 = g_csr_w[e + 1];
        float c2 = g_csr_w[e + 2], c3 = g_csr_w[e + 3];
        float4 v0 = *(const float4*)&g_h2[s0 * CC + 4 * q];
        float4 v1 = *(const float4*)&g_h2[s1 * CC + 4 * q];
        float4 v2 = *(const float4*)&g_h2[s2 * CC + 4 * q];
        float4 v3 = *(const float4*)&g_h2[s3 * CC + 4 * q];
        acc.x += c0 * v0.x + c1 * v1.x + c2 * v2.x + c3 * v3.x;
        acc.y += c0 * v0.y + c1 * v1.y + c2 * v2.y + c3 * v3.y;
        acc.z += c0 * v0.z + c1 * v1.z + c2 * v2.z + c3 * v3.z;
        acc.w += c0 * v0.w + c1 * v1.w + c2 * v2.w + c3 * v3.w;
    }
    for (; e < end; e++) {
        int s = g_csr_src[e];
        float c = g_csr_w[e];
        float4 v0 = *(const float4*)&g_h2[s * CC + 4 * q];
        acc.x += c * v0.x; acc.y += c * v0.y;
        acc.z += c * v0.z; acc.w += c * v0.w;
    }

    float4 bv = ((const float4*)b2)[q];
    acc.x += bv.x; acc.y += bv.y; acc.z += bv.z; acc.w += bv.w;

    float m = fmaxf(fmaxf(acc.x, acc.y), fmaxf(acc.z, acc.w));
    m = fmaxf(m, __shfl_xor_sync(0xffffffffu, m, 1, 4));
    m = fmaxf(m, __shfl_xor_sync(0xffffffffu, m, 2, 4));
    float s = expf(acc.x - m) + expf(acc.y - m) + expf(acc.z - m) + expf(acc.w - m);
    s += __shfl_xor_sync(0xffffffffu, s, 1, 4);
    s += __shfl_xor_sync(0xffffffffu, s, 2, 4);
    float ls = m + logf(s);

    float4 o = make_float4(acc.x - ls, acc.y - ls, acc.z - ls, acc.w - ls);
    *(float4*)&out[node * CC + 4 * q] = o;
}

// ================= launcher =================

extern "C" void kernel_launch(void* const* d_in, const int* in_sizes, int n_in,
                              void* d_out, int out_size) {
    const float* x  = (const float*)d_in[0];
    const float* W1 = (const float*)d_in[1];
    const float* b1 = (const float*)d_in[2];
    const float* W2 = (const float*)d_in[3];
    const float* b2 = (const float*)d_in[4];
    const int*   ei = (const int*)d_in[5];
    const int* src = ei;
    const int* dst = ei + EE;
    float* out = (float*)d_out;

    // CSR build
    k_zero<<<(NN + 255) / 256, 256>>>();
    k_count<<<(EE + 255) / 256, 256>>>(dst);
    k_scan1<<<NCHUNK, SCAN_B>>>();
    k_scan2<<<1, 128>>>();
    k_scan3<<<NCHUNK, SCAN_B>>>();
    k_scatter<<<(EE + 255) / 256, 256>>>(src, dst);

    // layer 1
    k_gemm1<<<(NN + 63) / 64, 256>>>(x, W1);
    k_prop1<<<(NN * 32 + 255) / 256, 256>>>();

    // layer 2 + output
    k_gemm2<<<(NN + 63) / 64, 256>>>(b1, W2);
    k_prop2_final<<<(NN * 4 + 255) / 256, 256>>>(b2, out);
}

// round 12
// speedup vs baseline: 1.5356x; 1.0611x over previous
#include <cuda_runtime.h>
#include <cstdint>

#define NN 50000
#define EE 800000
#define FIN 128
#define HH 100
#define CC 16
#define SCAN_B 512
#define NCHUNK ((NN + SCAN_B - 1) / SCAN_B)   // 98

// ---- scratch (device globals; no allocations) ----
__device__ float g_dinv[NN];
__device__ int   g_cnt[NN];
__device__ int   g_incl[NN];
__device__ int   g_bsum[NCHUNK];
__device__ int   g_boff[NCHUNK];
__device__ int   g_rowptr[NN + 1];
__device__ int   g_cur[NN];
__device__ int   g_csr_src[EE];
__device__ float g_csr_w[EE];
__device__ float g_h1[NN * HH];       // x @ W1
__device__ float g_h1p[NN * HH];      // propagated layer-1
__device__ float g_h2[NN * CC];       // a1 @ W2

// ================= CSR build =================

__global__ void k_zero() {
    int i = blockIdx.x * blockDim.x + threadIdx.x;
    if (i < NN) g_cnt[i] = 0;
}

__global__ void k_count(const int* __restrict__ dst) {
    int e = blockIdx.x * blockDim.x + threadIdx.x;
    if (e < EE) atomicAdd(&g_cnt[dst[e]], 1);
}

__global__ __launch_bounds__(SCAN_B) void k_scan1() {
    __shared__ int sh[SCAN_B];
    int t = threadIdx.x;
    int i = blockIdx.x * SCAN_B + t;
    int v = (i < NN) ? g_cnt[i] : 0;
    sh[t] = v;
    __syncthreads();
#pragma unroll
    for (int off = 1; off < SCAN_B; off <<= 1) {
        int a = (t >= off) ? sh[t - off] : 0;
        __syncthreads();
        sh[t] += a;
        __syncthreads();
    }
    if (i < NN) g_incl[i] = sh[t];
    if (t == SCAN_B - 1) g_bsum[blockIdx.x] = sh[t];
}

__global__ __launch_bounds__(128) void k_scan2() {
    __shared__ int sh[128];
    int t = threadIdx.x;
    int v = (t < NCHUNK) ? g_bsum[t] : 0;
    sh[t] = v;
    __syncthreads();
#pragma unroll
    for (int off = 1; off < 128; off <<= 1) {
        int a = (t >= off) ? sh[t - off] : 0;
        __syncthreads();
        sh[t] += a;
        __syncthreads();
    }
    if (t < NCHUNK) g_boff[t] = sh[t] - v;   // exclusive
}

__global__ __launch_bounds__(SCAN_B) void k_scan3() {
    int i = blockIdx.x * SCAN_B + threadIdx.x;
    if (i < NN) {
        int cnt = g_cnt[i];
        int excl = g_incl[i] - cnt + g_boff[blockIdx.x];
        g_rowptr[i] = excl;
        g_cur[i] = excl;
        g_dinv[i] = rsqrtf((float)(cnt + 1));  // +1 self loop
    }
    if (i == 0) g_rowptr[NN] = EE;
}

__global__ void k_scatter(const int* __restrict__ src, const int* __restrict__ dst) {
    int e = blockIdx.x * blockDim.x + threadIdx.x;
    if (e >= EE) return;
    int s = src[e], d = dst[e];
    int pos = atomicAdd(&g_cur[d], 1);
    g_csr_src[pos] = s;
    g_csr_w[pos] = g_dinv[s] * g_dinv[d];
}

// ================ GEMM1: h1 = x @ W1 via 3xTF32 mma.sync ================
// Block: 64 rows x 104 cols (13 n-tiles of 8), 128 threads (4 warps).
// Warp = 16 rows x 104 cols. K in two 64-wide halves (smem 44KB static).

__device__ __forceinline__ void mma_tf32(float* c, const uint32_t* a, const uint32_t* b) {
    asm volatile(
        "mma.sync.aligned.m16n8k8.row.col.f32.tf32.tf32.f32 "
        "{%0,%1,%2,%3}, {%4,%5,%6,%7}, {%8,%9}, {%0,%1,%2,%3};"
        : "+f"(c[0]), "+f"(c[1]), "+f"(c[2]), "+f"(c[3])
        : "r"(a[0]), "r"(a[1]), "r"(a[2]), "r"(a[3]), "r"(b[0]), "r"(b[1]));
}

__device__ __forceinline__ void split_tf32(float x, uint32_t& hi, uint32_t& lo) {
    uint32_t h;
    asm("cvt.rna.tf32.f32 %0, %1;" : "=r"(h) : "f"(x));
    float l = x - __uint_as_float(h);
    uint32_t lw;
    asm("cvt.rna.tf32.f32 %0, %1;" : "=r"(lw) : "f"(l));
    hi = h; lo = lw;
}

__global__ __launch_bounds__(128) void k_gemm1(const float* __restrict__ x,
                                               const float* __restrict__ W1) {
    __shared__ float As[64][68];     // 64 rows x 64 k (pad 68 -> bank shift 4)
    __shared__ float Bs[64][104];    // 64 k x 104 cols (pad cols 100..103 = 0)

    const int tid  = threadIdx.x;
    const int warp = tid >> 5;
    const int lane = tid & 31;
    const int gid  = lane >> 2;      // 0..7
    const int tig  = lane & 3;       // 0..3
    const int m0   = blockIdx.x * 64;
    const int r0   = warp * 16;

    float acc[13][4];
#pragma unroll
    for (int n = 0; n < 13; n++)
#pragma unroll
        for (int j = 0; j < 4; j++) acc[n][j] = 0.0f;

#pragma unroll
    for (int kh = 0; kh < 2; kh++) {
        // load A half: 64 rows x 64 k = 1024 float4, 8 per thread
#pragma unroll
        for (int u = 0; u < 8; u++) {
            int idx = tid + u * 128;        // 0..1023
            int row = idx >> 4;             // 0..63
            int j   = idx & 15;             // 16 float4 per row
            int gr = m0 + row;
            float4 v = make_float4(0.f, 0.f, 0.f, 0.f);
            if (gr < NN) v = *(const float4*)&x[gr * FIN + kh * 64 + j * 4];
            *(float4*)&As[row][j * 4] = v;
        }
        // load B half: 64 k-rows x 100 cols (25 float4/row), 1600 f4 total
#pragma unroll
        for (int u = 0; u < 13; u++) {
            int idx = tid + u * 128;        // 0..1663
            if (idx < 1600) {
                int k = idx / 25;
                int j = idx - k * 25;
                float4 v = *(const float4*)&W1[(kh * 64 + k) * HH + j * 4];
                *(float4*)&Bs[k][j * 4] = v;
            }
        }
        // zero pad cols 100..103 (64 rows x 4 = 256 floats, 2 per thread)
        {
            int k = tid >> 1;
            int c = 100 + ((tid & 1) << 1);
            Bs[k][c] = 0.0f;
            Bs[k][c + 1] = 0.0f;
        }
        __syncthreads();

#pragma unroll
        for (int kt = 0; kt < 8; kt++) {
            int k0 = kt * 8;
            // A fragment (m16 x k8), split hi/lo
            float af[4];
            af[0] = As[r0 + gid][k0 + tig];
            af[1] = As[r0 + gid + 8][k0 + tig];
            af[2] = As[r0 + gid][k0 + tig + 4];
            af[3] = As[r0 + gid + 8][k0 + tig + 4];
            uint32_t ahi[4], alo[4];
#pragma unroll
            for (int j = 0; j < 4; j++) split_tf32(af[j], ahi[j], alo[j]);

#pragma unroll
            for (int nt = 0; nt < 13; nt++) {
                int n0 = nt * 8;
                float bf0 = Bs[k0 + tig][n0 + gid];
                float bf1 = Bs[k0 + tig + 4][n0 + gid];
                uint32_t bhi[2], blo[2];
                split_tf32(bf0, bhi[0], blo[0]);
                split_tf32(bf1, bhi[1], blo[1]);
                mma_tf32(acc[nt], ahi, bhi);
                mma_tf32(acc[nt], ahi, blo);
                mma_tf32(acc[nt], alo, bhi);
            }
        }
        __syncthreads();
    }

    // store: rows m0+r0+gid (+8), cols nt*8 + 2*tig (+1)
    int ra = m0 + r0 + gid;
    int rb = ra + 8;
#pragma unroll
    for (int nt = 0; nt < 13; nt++) {
        int c = nt * 8 + 2 * tig;
        if (c < HH) {
            if (ra < NN) {
                g_h1[ra * HH + c] = acc[nt][0];
                g_h1[ra * HH + c + 1] = acc[nt][1];
            }
            if (rb < NN) {
                g_h1[rb * HH + c] = acc[nt][2];
                g_h1[rb * HH + c + 1] = acc[nt][3];
            }
        }
    }
}

// ============ prop1: gather per destination node (warp/node) ============

__global__ __launch_bounds__(256) void k_prop1() {
    int w = (blockIdx.x * blockDim.x + threadIdx.x) >> 5;
    int lane = threadIdx.x & 31;
    if (w >= NN) return;
    int beg = g_rowptr[w];
    int end = g_rowptr[w + 1];
    float dv = g_dinv[w];
    float sc = dv * dv;                       // self-loop coefficient
    const float* sr = g_h1 + w * HH;
    bool tail = (lane < HH - 96);

    float a0 = sr[lane] * sc;
    float a1 = sr[32 + lane] * sc;
    float a2 = sr[64 + lane] * sc;
    float a3 = tail ? sr[96 + lane] * sc : 0.f;

    int e = beg;
    for (; e + 4 <= end; e += 4) {
        int s0 = g_csr_src[e],     s1 = g_csr_src[e + 1];
        int s2 = g_csr_src[e + 2], s3 = g_csr_src[e + 3];
        float c0 = g_csr_w[e],     c1 = g_csr_w[e + 1];
        float c2 = g_csr_w[e + 2], c3 = g_csr_w[e + 3];
        const float* r0 = g_h1 + s0 * HH;
        const float* r1 = g_h1 + s1 * HH;
        const float* r2 = g_h1 + s2 * HH;
        const float* r3 = g_h1 + s3 * HH;
        float x00 = r0[lane], x01 = r0[32 + lane], x02 = r0[64 + lane];
        float x10 = r1[lane], x11 = r1[32 + lane], x12 = r1[64 + lane];
        float x20 = r2[lane], x21 = r2[32 + lane], x22 = r2[64 + lane];
        float x30 = r3[lane], x31 = r3[32 + lane], x32 = r3[64 + lane];
        float x03 = tail ? r0[96 + lane] : 0.f;
        float x13 = tail ? r1[96 + lane] : 0.f;
        float x23 = tail ? r2[96 + lane] : 0.f;
        float x33 = tail ? r3[96 + lane] : 0.f;
        a0 += c0 * x00 + c1 * x10 + c2 * x20 + c3 * x30;
        a1 += c0 * x01 + c1 * x11 + c2 * x21 + c3 * x31;
        a2 += c0 * x02 + c1 * x12 + c2 * x22 + c3 * x32;
        a3 += c0 * x03 + c1 * x13 + c2 * x23 + c3 * x33;
    }
    for (; e < end; e++) {
        int s = g_csr_src[e];
        float c = g_csr_w[e];
        const float* r = g_h1 + s * HH;
        a0 += c * r[lane];
        a1 += c * r[32 + lane];
        a2 += c * r[64 + lane];
        if (tail) a3 += c * r[96 + lane];
    }

    float* o = g_h1p + w * HH;
    o[lane] = a0;
    o[32 + lane] = a1;
    o[64 + lane] = a2;
    if (tail) o[96 + lane] = a3;
}

// ===== GEMM2: h2 = leaky(h1p + b1) @ W2  (50000x100 @ 100x16) =====

__global__ __launch_bounds__(256) void k_gemm2(const float* __restrict__ b1,
                                               const float* __restrict__ W2) {
    __shared__ float w2s[HH * CC];      // [k][c] row-major, 1600 floats
    __shared__ float a1s[64][HH];       // 6400 floats
    int tid = threadIdx.x;
    int r0  = blockIdx.x * 64;

    for (int i = tid; i < HH * CC; i += 256) w2s[i] = W2[i];
#pragma unroll
    for (int u = 0; u < 25; u++) {
        int i = tid + u * 256;          // 0..6399
        int r = i / HH, c = i % HH;
        int gr = r0 + r;
        float v = 0.0f;
        if (gr < NN) {
            v = g_h1p[gr * HH + c] + b1[c];
            v = (v > 0.0f) ? v : 0.01f * v;
        }
        a1s[r][c] = v;
    }
    __syncthreads();

    int r = tid >> 2;        // 0..63
    int q = tid & 3;         // 0..3 -> cols 4q..4q+3
    float4 acc = make_float4(0.f, 0.f, 0.f, 0.f);
#pragma unroll
    for (int k = 0; k < HH; k++) {
        float a = a1s[r][k];
        float4 w = *(const float4*)&w2s[k * CC + 4 * q];
        acc.x += a * w.x;
        acc.y += a * w.y;
        acc.z += a * w.z;
        acc.w += a * w.w;
    }
    int gr = r0 + r;
    if (gr < NN) *(float4*)&g_h2[gr * CC + 4 * q] = acc;
}

// ===== prop2 + bias + log_softmax fused (4 threads per node) =====

__global__ __launch_bounds__(256) void k_prop2_final(const float* __restrict__ b2,
                                                     float* __restrict__ out) {
    int t = blockIdx.x * blockDim.x + threadIdx.x;
    int node = t >> 2;
    int q = t & 3;
    if (node >= NN) return;

    int beg = g_rowptr[node];
    int end = g_rowptr[node + 1];
    float dv = g_dinv[node];
    float sc = dv * dv;

    float4 v = *(const float4*)&g_h2[node * CC + 4 * q];
    float4 acc = make_float4(v.x * sc, v.y * sc, v.z * sc, v.w * sc);

    int e = beg;
    for (; e + 4 <= end; e += 4) {
        int s0 = g_csr_src[e],     s1 = g_csr_src[e + 1];
        int s2 = g_csr_src[e + 2], s3 = g_csr_src[e + 3];
        float c0 = g_csr_w[e],     c1 = g_csr_w[e + 1];
        float c2 = g_csr_w[e + 2], c3 = g_csr_w[e + 3];
        float4 v0 = *(const float4*)&g_h2[s0 * CC + 4 * q];
        float4 v1 = *(const float4*)&g_h2[s1 * CC + 4 * q];
        float4 v2 = *(const float4*)&g_h2[s2 * CC + 4 * q];
        float4 v3 = *(const float4*)&g_h2[s3 * CC + 4 * q];
        acc.x += c0 * v0.x + c1 * v1.x + c2 * v2.x + c3 * v3.x;
        acc.y += c0 * v0.y + c1 * v1.y + c2 * v2.y + c3 * v3.y;
        acc.z += c0 * v0.z + c1 * v1.z + c2 * v2.z + c3 * v3.z;
        acc.w += c0 * v0.w + c1 * v1.w + c2 * v2.w + c3 * v3.w;
    }
    for (; e < end; e++) {
        int s = g_csr_src[e];
        float c = g_csr_w[e];
        float4 v0 = *(const float4*)&g_h2[s * CC + 4 * q];
        acc.x += c * v0.x; acc.y += c * v0.y;
        acc.z += c * v0.z; acc.w += c * v0.w;
    }

    float4 bv = ((const float4*)b2)[q];
    acc.x += bv.x; acc.y += bv.y; acc.z += bv.z; acc.w += bv.w;

    float m = fmaxf(fmaxf(acc.x, acc.y), fmaxf(acc.z, acc.w));
    m = fmaxf(m, __shfl_xor_sync(0xffffffffu, m, 1, 4));
    m = fmaxf(m, __shfl_xor_sync(0xffffffffu, m, 2, 4));
    float s = expf(acc.x - m) + expf(acc.y - m) + expf(acc.z - m) + expf(acc.w - m);
    s += __shfl_xor_sync(0xffffffffu, s, 1, 4);
    s += __shfl_xor_sync(0xffffffffu, s, 2, 4);
    float ls = m + logf(s);

    float4 o = make_float4(acc.x - ls, acc.y - ls, acc.z - ls, acc.w - ls);
    *(float4*)&out[node * CC + 4 * q] = o;
}

// ================= launcher =================

extern "C" void kernel_launch(void* const* d_in, const int* in_sizes, int n_in,
                              void* d_out, int out_size) {
    const float* x  = (const float*)d_in[0];
    const float* W1 = (const float*)d_in[1];
    const float* b1 = (const float*)d_in[2];
    const float* W2 = (const float*)d_in[3];
    const float* b2 = (const float*)d_in[4];
    const int*   ei = (const int*)d_in[5];
    const int* src = ei;
    const int* dst = ei + EE;
    float* out = (float*)d_out;

    // CSR build
    k_zero<<<(NN + 255) / 256, 256>>>();
    k_count<<<(EE + 255) / 256, 256>>>(dst);
    k_scan1<<<NCHUNK, SCAN_B>>>();
    k_scan2<<<1, 128>>>();
    k_scan3<<<NCHUNK, SCAN_B>>>();
    k_scatter<<<(EE + 255) / 256, 256>>>(src, dst);

    // layer 1
    k_gemm1<<<(NN + 63) / 64, 128>>>(x, W1);
    k_prop1<<<(NN * 32 + 255) / 256, 256>>>();

    // layer 2 + output
    k_gemm2<<<(NN + 63) / 64, 256>>>(b1, W2);
    k_prop2_final<<<(NN * 4 + 255) / 256, 256>>>(b2, out);
}